// round 17
// baseline (speedup 1.0000x reference)
#include <cuda_runtime.h>
#include <cuda_fp16.h>
#include <math.h>

#define NB   1024
#define NR   2336
#define NK   2
#define NBLK (NB)                   // fused grid size (NB/2 batch-pairs * NK)
// Cin = 4, Cout = 16 (fixed)

__device__ float g_cls[NB * NK];
__device__ int   g_done = 0;
// Pre-converted fp16 W: per (k,r,q): 16 halfs (i=0..3 x out-in-quad 0..3) = 32 B
// index: ((k*NR + r)*4 + q) * 2 uint4
__device__ uint4 g_W16[(size_t)NK * NR * 4 * 2];

// ---------------------------------------------------------------------------
// W conversion kernel: f32 -> packed fp16, quad-contiguous layout.
// ---------------------------------------------------------------------------
__global__ void conv_w_kernel(const float4* __restrict__ W4)
{
    int idx = blockIdx.x * blockDim.x + threadIdx.x;   // (k*NR+r)*4 + q
    if (idx < NK * NR * 4) {
        int q  = idx & 3;
        int kr = idx >> 2;
        const float4* wp = W4 + (size_t)kr * 16 + q;
        float4 w0 = __ldg(wp);      float4 w1 = __ldg(wp + 4);
        float4 w2 = __ldg(wp + 8);  float4 w3 = __ldg(wp + 12);
        __half2 h0 = __floats2half2_rn(w0.x, w0.y), h1 = __floats2half2_rn(w0.z, w0.w);
        __half2 h2 = __floats2half2_rn(w1.x, w1.y), h3 = __floats2half2_rn(w1.z, w1.w);
        __half2 h4 = __floats2half2_rn(w2.x, w2.y), h5 = __floats2half2_rn(w2.z, w2.w);
        __half2 h6 = __floats2half2_rn(w3.x, w3.y), h7 = __floats2half2_rn(w3.z, w3.w);
        uint4 p0, p1;
        p0.x = *(unsigned*)&h0; p0.y = *(unsigned*)&h1;
        p0.z = *(unsigned*)&h2; p0.w = *(unsigned*)&h3;
        p1.x = *(unsigned*)&h4; p1.y = *(unsigned*)&h5;
        p1.z = *(unsigned*)&h6; p1.w = *(unsigned*)&h7;
        g_W16[(size_t)idx * 2]     = p0;
        g_W16[(size_t)idx * 2 + 1] = p1;
    }
}

// ---------------------------------------------------------------------------
// Fused kernel: projection + routing + (last CTA) final softmax.
// TWO batches per CTA (same k), 1024 threads. u_ji tiles in smem fp16
// half-planes: per batch planeA (quads 0-1, 16 B/route) | 64 B pad | planeB;
// A->B offset == 64 (mod 128) => stores and per-route LDS.128 conflict-free.
// ---------------------------------------------------------------------------
#define PB_OFF      37440
#define TILE_BYTES  74816
#define P0_OFF      0
#define P1_OFF      TILE_BYTES
#define BS0_OFF     (2*TILE_BYTES)          // fp32 logits b[r], batch 0
#define BS1_OFF     (BS0_OFF + NR*4)
#define RED0_OFF    (BS1_OFF + NR*4)        // batch0: 5120 B (128 f4 / 16x20 f)
#define RED1_OFF    (RED0_OFF + 5120)       // batch1
#define V0_OFF      (RED1_OFF + 5120)       // 4 float4
#define V1_OFF      (V0_OFF + 64)
#define CLS0_OFF    (V1_OFF + 64)
#define CLS1_OFF    (CLS0_OFF + 4)
#define FLAG_OFF    (CLS1_OFF + 4)
#define SMEM_BYTES  (FLAG_OFF + 8)          // ~179.4 KB -> 1 CTA/SM

__device__ __forceinline__ void squash_store(const float4* red, float4* v4s,
                                             float* clsp, float cn)
{
    float s[16];
#pragma unroll
    for (int qq = 0; qq < 4; qq++) {
        float4 a = red[qq];
        s[qq*4+0] = a.x * cn; s[qq*4+1] = a.y * cn;
        s[qq*4+2] = a.z * cn; s[qq*4+3] = a.w * cn;
    }
    float n = 0.f;
#pragma unroll
    for (int o = 0; o < 16; o++) n += s[o] * s[o];
    // squash: v = (n/(1+n)) * s / sqrt(n);  |v| = n/(1+n)
    float f = n / ((1.f + n) * sqrtf(fmaxf(n, 1e-30f)));
#pragma unroll
    for (int qq = 0; qq < 4; qq++)
        v4s[qq] = make_float4(f*s[qq*4+0], f*s[qq*4+1], f*s[qq*4+2], f*s[qq*4+3]);
    *clsp = n / (1.f + n);
}

#define XOR_RED4(a, off) do { \
    a.x += __shfl_xor_sync(0xffffffffu, a.x, off); \
    a.y += __shfl_xor_sync(0xffffffffu, a.y, off); \
    a.z += __shfl_xor_sync(0xffffffffu, a.z, off); \
    a.w += __shfl_xor_sync(0xffffffffu, a.w, off); } while (0)

#define H2F2(dst, i, hw) do { \
    float2 _f = __half22float2(*reinterpret_cast<const __half2*>(&(hw))); \
    dst[i] = _f.x; dst[(i)+1] = _f.y; } while (0)

// Phase-1 body: thread (g = route-in-chunk, q = out-quad) computes one quad
// for BOTH batches. W read as packed fp16 (32 B), u as f32.
#define PROJ2(r) do { \
    const uint4* wp = w16 + (size_t)(r) * 8 + q * 2; \
    uint4 hw0 = __ldg(wp); uint4 hw1 = __ldg(wp + 1); \
    float4 uu0 = __ldg(&ub0[(r)]); \
    float4 uu1 = __ldg(&ub1[(r)]); \
    float w[16]; \
    H2F2(w, 0,  hw0.x); H2F2(w, 2,  hw0.y); \
    H2F2(w, 4,  hw0.z); H2F2(w, 6,  hw0.w); \
    H2F2(w, 8,  hw1.x); H2F2(w, 10, hw1.y); \
    H2F2(w, 12, hw1.z); H2F2(w, 14, hw1.w); \
    float4 o0, o1; \
    o0.x = fmaf(uu0.x,w[0], fmaf(uu0.y,w[4], fmaf(uu0.z,w[8],  uu0.w*w[12]))); \
    o0.y = fmaf(uu0.x,w[1], fmaf(uu0.y,w[5], fmaf(uu0.z,w[9],  uu0.w*w[13]))); \
    o0.z = fmaf(uu0.x,w[2], fmaf(uu0.y,w[6], fmaf(uu0.z,w[10], uu0.w*w[14]))); \
    o0.w = fmaf(uu0.x,w[3], fmaf(uu0.y,w[7], fmaf(uu0.z,w[11], uu0.w*w[15]))); \
    o1.x = fmaf(uu1.x,w[0], fmaf(uu1.y,w[4], fmaf(uu1.z,w[8],  uu1.w*w[12]))); \
    o1.y = fmaf(uu1.x,w[1], fmaf(uu1.y,w[5], fmaf(uu1.z,w[9],  uu1.w*w[13]))); \
    o1.z = fmaf(uu1.x,w[2], fmaf(uu1.y,w[6], fmaf(uu1.z,w[10], uu1.w*w[14]))); \
    o1.w = fmaf(uu1.x,w[3], fmaf(uu1.y,w[7], fmaf(uu1.z,w[11], uu1.w*w[15]))); \
    acc0.x += o0.x; acc0.y += o0.y; acc0.z += o0.z; acc0.w += o0.w; \
    acc1.x += o1.x; acc1.y += o1.y; acc1.z += o1.z; acc1.w += o1.w; \
    __half2 hA0 = __floats2half2_rn(o0.x, o0.y); \
    __half2 hB0 = __floats2half2_rn(o0.z, o0.w); \
    __half2 hA1 = __floats2half2_rn(o1.x, o1.y); \
    __half2 hB1 = __floats2half2_rn(o1.z, o1.w); \
    uint2 hv0, hv1; \
    hv0.x = *reinterpret_cast<unsigned*>(&hA0); \
    hv0.y = *reinterpret_cast<unsigned*>(&hB0); \
    hv1.x = *reinterpret_cast<unsigned*>(&hA1); \
    hv1.y = *reinterpret_cast<unsigned*>(&hB1); \
    dst0[(size_t)(r) * 2] = hv0; \
    dst1[(size_t)(r) * 2] = hv1; } while (0)

__global__ void __launch_bounds__(1024, 1) caps_fused_kernel(
    const float4* __restrict__ u4,   // u as float4: [b*NR + r]
    float*        __restrict__ out)  // final output [NB, NK]
{
    extern __shared__ char smb[];
    const int t = threadIdx.x;
    const int lane = t & 31, warp = t >> 5;
    const int cid = blockIdx.x;
    const int k  = cid & 1;
    const int b0 = (cid >> 1) * 2;           // batches b0, b0+1

    const float4* ub0 = u4 + (size_t)b0 * NR;
    const float4* ub1 = ub0 + NR;
    const uint4*  w16 = g_W16 + (size_t)k * NR * 8;

    float4* red0  = (float4*)(smb + RED0_OFF);
    float4* red1  = (float4*)(smb + RED1_OFF);
    float4* v4s0  = (float4*)(smb + V0_OFF);
    float4* v4s1  = (float4*)(smb + V1_OFF);

    // --- Phase 1: projection -> fp16 planes, fused sweep-1 (uniform c) ---
    const int q = t & 3;                     // out-quad
    const int g = t >> 2;                    // route-in-chunk 0..255
    uint2* dst0 = (uint2*)(smb + P0_OFF + (q < 2 ? 0 : PB_OFF)) + (q & 1);
    uint2* dst1 = (uint2*)(smb + P1_OFF + (q < 2 ? 0 : PB_OFF)) + (q & 1);

    float4 acc0 = make_float4(0.f,0.f,0.f,0.f);
    float4 acc1 = make_float4(0.f,0.f,0.f,0.f);
#pragma unroll 2
    for (int c = 0; c < 9; c++) {            // 9*256 = 2304 routes
        int r = c * 256 + g;
        PROJ2(r);
    }
    if (g < 32) {                            // tail: routes 2304..2335
        int r = 2304 + g;
        PROJ2(r);
    }

    // reduce acc across threads sharing q (8 per warp, 32 warps)
    XOR_RED4(acc0, 4); XOR_RED4(acc0, 8); XOR_RED4(acc0, 16);
    XOR_RED4(acc1, 4); XOR_RED4(acc1, 8); XOR_RED4(acc1, 16);
    if (lane < 4) { red0[warp*4 + lane] = acc0; red1[warp*4 + lane] = acc1; }
    __syncthreads();
    if (warp < 2) {                          // warp0 -> batch0, warp1 -> batch1
        float4* rg = warp ? red1 : red0;
        float4 a = rg[lane];
#pragma unroll
        for (int j = 32; j < 128; j += 32) {
            float4 bx = rg[lane + j];
            a.x += bx.x; a.y += bx.y; a.z += bx.z; a.w += bx.w;
        }
        XOR_RED4(a, 4); XOR_RED4(a, 8); XOR_RED4(a, 16);
        if (lane < 4) rg[lane] = a;
        __syncwarp();
        if (lane == 0)
            squash_store(rg, warp ? v4s1 : v4s0,
                         (float*)(smb + (warp ? CLS1_OFF : CLS0_OFF)),
                         1.f / (float)NR);
    }
    __syncthreads();

    // --- Phase 2: two fused (b-update + softmax s-sweep) iterations ---
    // warps 0-15 -> batch 0, warps 16-31 -> batch 1; thread-per-route.
    const int grp = warp >> 4;
    const int tt  = t & 511;
    const uint4* pA = (const uint4*)(smb + (grp ? P1_OFF : P0_OFF));
    const uint4* pB = (const uint4*)(smb + (grp ? P1_OFF : P0_OFF) + PB_OFF);
    float* bs     = (float*)(smb + (grp ? BS1_OFF : BS0_OFF));
    float* redf   = (float*)(smb + (grp ? RED1_OFF : RED0_OFF));
    float4* v4sg  = grp ? v4s1 : v4s0;

#pragma unroll
    for (int it = 0; it < 2; it++) {
        float vv[16];
        {
            float4 t0 = v4sg[0], t1 = v4sg[1], t2 = v4sg[2], t3 = v4sg[3];
            vv[0]=t0.x; vv[1]=t0.y; vv[2]=t0.z; vv[3]=t0.w;
            vv[4]=t1.x; vv[5]=t1.y; vv[6]=t1.z; vv[7]=t1.w;
            vv[8]=t2.x; vv[9]=t2.y; vv[10]=t2.z; vv[11]=t2.w;
            vv[12]=t3.x; vv[13]=t3.y; vv[14]=t3.z; vv[15]=t3.w;
        }
        float a[17];                          // 16 accum + Z
#pragma unroll
        for (int o = 0; o < 17; o++) a[o] = 0.f;

#pragma unroll 2
        for (int r = tt; r < NR; r += 512) {
            uint4 ha = pA[r];                // quads 0-1 (8 halfs)
            uint4 hb = pB[r];                // quads 2-3
            float x[16];
            H2F2(x, 0,  ha.x); H2F2(x, 2,  ha.y);
            H2F2(x, 4,  ha.z); H2F2(x, 6,  ha.w);
            H2F2(x, 8,  hb.x); H2F2(x, 10, hb.y);
            H2F2(x, 12, hb.z); H2F2(x, 14, hb.w);
            // tree dot: 4 independent chains, depth ~6
            float d0 = fmaf(x[12], vv[12], fmaf(x[8],  vv[8],  fmaf(x[4],  vv[4],  x[0]*vv[0])));
            float d1 = fmaf(x[13], vv[13], fmaf(x[9],  vv[9],  fmaf(x[5],  vv[5],  x[1]*vv[1])));
            float d2 = fmaf(x[14], vv[14], fmaf(x[10], vv[10], fmaf(x[6],  vv[6],  x[2]*vv[2])));
            float d3 = fmaf(x[15], vv[15], fmaf(x[11], vv[11], fmaf(x[7],  vv[7],  x[3]*vv[3])));
            float d = (d0 + d1) + (d2 + d3);
            float bn;
            if (it == 0) { bn = d; bs[r] = d; }
            else         { bn = bs[r] + d; }
            float e = __expf(bn);            // logits bounded, no max-shift
            a[16] += e;
#pragma unroll
            for (int o = 0; o < 16; o++) a[o] = fmaf(e, x[o], a[o]);
        }

        // intra-warp reduce of 17 values
#pragma unroll
        for (int off = 1; off < 32; off <<= 1)
#pragma unroll
            for (int o = 0; o < 17; o++)
                a[o] += __shfl_xor_sync(0xffffffffu, a[o], off);
        if (lane == 0) {
            float* rp = redf + (warp & 15) * 20;
#pragma unroll
            for (int o = 0; o < 17; o++) rp[o] = a[o];
        }
        __syncthreads();
        if (warp < 2) {                      // warp0 -> batch0, warp1 -> batch1
            float* rf = (float*)(smb + (warp ? RED1_OFF : RED0_OFF));
            float tot = 0.f;
            if (lane < 17) {
#pragma unroll
                for (int w4 = 0; w4 < 16; w4++) tot += rf[w4*20 + lane];
            }
            __syncwarp();
            if (lane < 17) rf[lane] = tot;
            __syncwarp();
            if (lane == 0)
                squash_store((float4*)rf, warp ? v4s1 : v4s0,
                             (float*)(smb + (warp ? CLS1_OFF : CLS0_OFF)),
                             1.f / rf[16]);
        }
        __syncthreads();
    }

    // --- write class norms; last CTA computes the final 2-class softmax ---
    int* flag = (int*)(smb + FLAG_OFF);
    if (t == 0) {
        g_cls[(size_t)b0 * 2 + k]       = *(float*)(smb + CLS0_OFF);
        g_cls[(size_t)(b0 + 1) * 2 + k] = *(float*)(smb + CLS1_OFF);
        __threadfence();
        int old = atomicAdd(&g_done, 1);
        *flag = (old == NBLK - 1);
    }
    __syncthreads();
    if (*flag) {
        __threadfence();                      // acquire all g_cls writes
        int b = t;                            // 1024 threads, 1024 batches
        float c0 = g_cls[2*b], c1 = g_cls[2*b + 1];
        float m  = fmaxf(c0, c1);
        float e0 = expf(c0 - m), e1 = expf(c1 - m);
        float inv = 1.f / (e0 + e1);
        out[2*b]     = e0 * inv;
        out[2*b + 1] = e1 * inv;
        __syncthreads();
        if (t == 0) g_done = 0;               // reset for next graph replay
    }
}

// ---------------------------------------------------------------------------
extern "C" void kernel_launch(void* const* d_in, const int* in_sizes, int n_in,
                              void* d_out, int out_size)
{
    const float4* u4 = (const float4*)d_in[0];   // u: [1024,2336,4] f32
    const float4* W4 = (const float4*)d_in[1];   // W: [2,2336,4,16] f32
    (void)in_sizes; (void)n_in; (void)out_size;

    cudaFuncSetAttribute(caps_fused_kernel,
                         cudaFuncAttributeMaxDynamicSharedMemorySize, SMEM_BYTES);

    conv_w_kernel<<<(NK * NR * 4 + 255) / 256, 256>>>(W4);
    caps_fused_kernel<<<NBLK, 1024, SMEM_BYTES>>>(u4, (float*)d_out);
}